// round 3
// baseline (speedup 1.0000x reference)
#include <cuda_runtime.h>
#include <float.h>

// Chamfer-distance loss:
//   fwd = mean_i min_j ||pred_i - gt_j||^2 (clamped at 0)
//   bwd = mean_j min_i ||gt_j - pred_i||^2 (clamped at 0)
//   out = fwd + bwd
//
// d2 = p2 + (g2 - 2*dot). Per-query p2 hoisted out of the min (min and
// max(.,0) are monotone-compatible). Inner loop: 3-deep FMA chain per
// (query, target) pair, 2 targets at once via packed fp32x2 FFMA2
// (PTX fma.rn.f32x2, sm_100+), 4 queries per thread to amortize the
// 2 broadcast LDS.128 per target-pair.

#define TILE_T 1024              // targets per chunk (one smem tile = 16KB)
#define TILE_P (TILE_T / 2)      // target pairs per tile
#define MAXT   32768             // max padded targets supported
#define MAXP   (MAXT / 2)
#define MAXC   (MAXT / TILE_T)   // max chunks (32)
#define NQ     4                 // queries per thread
#define NTHR   256
#define QB     (NQ * NTHR)       // queries per block (1024)

// Scratch (static __device__ — no allocations allowed)
__device__ float g_tgt[2][MAXP][8];          // [dir][pair][{hx0,hx1,hy0,hy1,hz0,hz1,c0,c1}]
__device__ float g_minpart[2][MAXC][MAXT];   // [dir][chunk][query] partial mins (excl. p2)
__device__ float g_partsum[512];             // block partial sums for final reduce

// ---------- packed fp32x2 helpers ----------
__device__ __forceinline__ unsigned long long pack2(float a, float b) {
    unsigned long long r;
    asm("mov.b64 %0, {%1, %2};" : "=l"(r) : "f"(a), "f"(b));
    return r;
}
__device__ __forceinline__ void unpack2(unsigned long long v, float& a, float& b) {
    asm("mov.b64 {%0, %1}, %2;" : "=f"(a), "=f"(b) : "l"(v));
}
__device__ __forceinline__ unsigned long long fma2(unsigned long long a,
                                                   unsigned long long b,
                                                   unsigned long long c) {
    unsigned long long d;
    asm("fma.rn.f32x2 %0, %1, %2, %3;" : "=l"(d) : "l"(a), "l"(b), "l"(c));
    return d;
}

// ---------- prep: build pair-interleaved target buffers ----------
// dir 0 targets = gt (stride 4, first 3 cols), padded to padM with c=+huge
// dir 1 targets = pred (stride 3), padded to padN
__global__ void prep_kernel(const float* __restrict__ pred,
                            const float* __restrict__ gt,
                            int N, int M, int padN, int padM) {
    int t = blockIdx.x * blockDim.x + threadIdx.x;
    int dir, j, cnt, stride;
    const float* src;
    if (t < padM)              { dir = 0; j = t;        cnt = M; src = gt;   stride = 4; }
    else if (t < padM + padN)  { dir = 1; j = t - padM; cnt = N; src = pred; stride = 3; }
    else return;

    float x = 0.f, y = 0.f, z = 0.f, c = 1e30f;
    if (j < cnt) {
        x = src[j * stride + 0];
        y = src[j * stride + 1];
        z = src[j * stride + 2];
        c = x * x + y * y + z * z;
    }
    int p = j >> 1, l = j & 1;
    float* q = g_tgt[dir][p];
    q[0 + l] = -2.f * x;
    q[2 + l] = -2.f * y;
    q[4 + l] = -2.f * z;
    q[6 + l] = c;
}

// ---------- main: brute-force min over one target chunk per block ----------
__global__ __launch_bounds__(NTHR, 2)
void chamfer_main(const float* __restrict__ pred,
                  const float* __restrict__ gt,
                  int N, int M,
                  int nqb0, int nc0, int nqb1, int nc1) {
    int bx = blockIdx.x;
    int dir, qb, ch;
    if (bx < nqb0 * nc0) { dir = 0; qb = bx / nc0; ch = bx % nc0; }
    else { bx -= nqb0 * nc0; dir = 1; qb = bx / nc1; ch = bx % nc1; }

    // queries: dir0 -> pred (N, stride 3); dir1 -> gt (M, stride 4)
    int nq = dir ? M : N;
    const float* qs = dir ? gt : pred;
    int qstride = dir ? 4 : 3;

    // load target tile into shared (pair-interleaved, 32B per pair)
    __shared__ ulonglong2 s_tile[TILE_P][2];
    {
        const float4* src = (const float4*)&g_tgt[dir][ch * TILE_P][0];
        float4* dst = (float4*)&s_tile[0][0];
        #pragma unroll
        for (int i = threadIdx.x; i < TILE_P * 2; i += NTHR)
            dst[i] = src[i];
    }

    // per-thread queries: q, q+NTHR, q+2*NTHR, q+3*NTHR
    unsigned long long px[NQ], py[NQ], pz[NQ];
    int qidx[NQ];
    #pragma unroll
    for (int k = 0; k < NQ; k++) {
        int q = qb * QB + k * NTHR + threadIdx.x;
        qidx[k] = q;
        float x = 0.f, y = 0.f, z = 0.f;
        if (q < nq) {
            x = qs[q * qstride + 0];
            y = qs[q * qstride + 1];
            z = qs[q * qstride + 2];
        }
        px[k] = pack2(x, x);
        py[k] = pack2(y, y);
        pz[k] = pack2(z, z);
    }

    __syncthreads();

    float ma[NQ], mb[NQ];
    #pragma unroll
    for (int k = 0; k < NQ; k++) { ma[k] = FLT_MAX; mb[k] = FLT_MAX; }

    #pragma unroll 4
    for (int p = 0; p < TILE_P; p++) {
        // A = {hx0,hx1, hy0,hy1}, B = {hz0,hz1, c0,c1}
        ulonglong2 A = s_tile[p][0];
        ulonglong2 B = s_tile[p][1];

        #pragma unroll
        for (int k = 0; k < NQ; k++) {
            unsigned long long a = fma2(A.x, px[k], B.y);
            a = fma2(A.y, py[k], a);
            a = fma2(B.x, pz[k], a);
            float lo, hi; unpack2(a, lo, hi);
            ma[k] = fminf(ma[k], lo);
            mb[k] = fminf(mb[k], hi);
        }
    }

    #pragma unroll
    for (int k = 0; k < NQ; k++)
        if (qidx[k] < nq) g_minpart[dir][ch][qidx[k]] = fminf(ma[k], mb[k]);
}

// ---------- reduce1: min over chunks, add p2, relu, block-sum ----------
__global__ void reduce1_kernel(const float* __restrict__ pred,
                               const float* __restrict__ gt,
                               int N, int M, int nc0, int nc1) {
    int i = blockIdx.x * blockDim.x + threadIdx.x;
    float v = 0.f;
    int total = N + M;
    if (i < total) {
        int dir = (i < N) ? 0 : 1;
        int q = dir ? (i - N) : i;
        int nc = dir ? nc1 : nc0;
        float m = FLT_MAX;
        for (int c = 0; c < nc; c++)
            m = fminf(m, g_minpart[dir][c][q]);
        const float* qs = dir ? gt : pred;
        int st = dir ? 4 : 3;
        float x = qs[q * st + 0], y = qs[q * st + 1], z = qs[q * st + 2];
        float p2 = x * x + y * y + z * z;
        float w = dir ? (1.f / (float)M) : (1.f / (float)N);
        v = fmaxf(m + p2, 0.f) * w;
    }
    __shared__ float ssum[256];
    ssum[threadIdx.x] = v;
    __syncthreads();
    for (int s = 128; s > 0; s >>= 1) {
        if (threadIdx.x < s) ssum[threadIdx.x] += ssum[threadIdx.x + s];
        __syncthreads();
    }
    if (threadIdx.x == 0) g_partsum[blockIdx.x] = ssum[0];
}

// ---------- reduce2: sum block partials ----------
__global__ void reduce2_kernel(float* __restrict__ out, int nparts) {
    float s = 0.f;
    for (int i = threadIdx.x; i < nparts; i += 256)
        s += g_partsum[i];
    __shared__ float ssum[256];
    ssum[threadIdx.x] = s;
    __syncthreads();
    for (int st = 128; st > 0; st >>= 1) {
        if (threadIdx.x < st) ssum[threadIdx.x] += ssum[threadIdx.x + st];
        __syncthreads();
    }
    if (threadIdx.x == 0) out[0] = ssum[0];
}

extern "C" void kernel_launch(void* const* d_in, const int* in_sizes, int n_in,
                              void* d_out, int out_size) {
    const float* pred = (const float*)d_in[0];  // [N,3]
    const float* gt   = (const float*)d_in[1];  // [M,4]
    int N = in_sizes[0] / 3;
    int M = in_sizes[1] / 4;

    int padM = ((M + TILE_T - 1) / TILE_T) * TILE_T;  // dir0 targets
    int padN = ((N + TILE_T - 1) / TILE_T) * TILE_T;  // dir1 targets
    int nc0 = padM / TILE_T;
    int nc1 = padN / TILE_T;
    int nqb0 = (N + QB - 1) / QB;
    int nqb1 = (M + QB - 1) / QB;

    int prep_total = padM + padN;
    prep_kernel<<<(prep_total + 255) / 256, 256>>>(pred, gt, N, M, padN, padM);

    chamfer_main<<<nqb0 * nc0 + nqb1 * nc1, NTHR>>>(pred, gt, N, M, nqb0, nc0, nqb1, nc1);

    int total = N + M;
    int rblocks = (total + 255) / 256;
    reduce1_kernel<<<rblocks, 256>>>(pred, gt, N, M, nc0, nc1);
    reduce2_kernel<<<1, 256>>>((float*)d_out, rblocks);
}